// round 1
// baseline (speedup 1.0000x reference)
#include <cuda_runtime.h>
#include <math.h>

#define DD   1024
#define TT   4096
#define BB   4
#define BM   64
#define BN   64
#define BK   16
#define EPSF 1e-6f

// Row-block partials (deterministic two-stage reduction, no float atomics).
// (BB*TT)/BM = 256 row blocks, DD columns each.
__device__ float g_pk [256 * DD];
__device__ float g_pkv[256 * DD];
// Final stats: [B, D] each (D = H*HD flattened).
__device__ float g_ksum [BB * DD];
__device__ float g_kvsum[BB * DD];

__device__ __forceinline__ float phi_f(float x) {
    // elu(x)+1 : x>0 -> x+1 ; x<=0 -> exp(x)
    return x > 0.f ? x + 1.f : __expf(x);
}

// ---------------------------------------------------------------------------
// Kernel 1: k = phi(x@Wk^T), v = x@Wv^T computed tile-wise; reduce over the
// 64 rows of the tile -> per-rowblock partial k_sum / kv_sum.
// grid = (DD/BN, BB*TT/BM), 256 threads.
// ---------------------------------------------------------------------------
__global__ __launch_bounds__(256) void stats_kernel(
    const float* __restrict__ X,
    const float* __restrict__ Wk,
    const float* __restrict__ Wv)
{
    __shared__ float Xs[BK][BM + 4];
    __shared__ float Ks[BK][BN + 4];
    __shared__ float Vs[BK][BN + 4];
    __shared__ float redk [16][BN];
    __shared__ float redkv[16][BN];

    const int tid  = threadIdx.x;
    const int tx   = tid & 15;
    const int ty   = tid >> 4;
    const int row0 = blockIdx.y * BM;
    const int col0 = blockIdx.x * BN;

    const int lm = tid & 63;          // row (X) / out-col (W) index for loads
    const int lk = (tid >> 6) << 2;   // k sub-offset: 0,4,8,12

    const float* xp = X  + (size_t)(row0 + lm) * DD + lk;
    const float* kp = Wk + (size_t)(col0 + lm) * DD + lk;
    const float* vp = Wv + (size_t)(col0 + lm) * DD + lk;

    float accK[4][4], accV[4][4];
#pragma unroll
    for (int r = 0; r < 4; r++)
#pragma unroll
        for (int c = 0; c < 4; c++) { accK[r][c] = 0.f; accV[r][c] = 0.f; }

    for (int k0 = 0; k0 < DD; k0 += BK) {
        float4 xa = *(const float4*)(xp + k0);
        float4 ka = *(const float4*)(kp + k0);
        float4 va = *(const float4*)(vp + k0);
        Xs[lk + 0][lm] = xa.x; Xs[lk + 1][lm] = xa.y; Xs[lk + 2][lm] = xa.z; Xs[lk + 3][lm] = xa.w;
        Ks[lk + 0][lm] = ka.x; Ks[lk + 1][lm] = ka.y; Ks[lk + 2][lm] = ka.z; Ks[lk + 3][lm] = ka.w;
        Vs[lk + 0][lm] = va.x; Vs[lk + 1][lm] = va.y; Vs[lk + 2][lm] = va.z; Vs[lk + 3][lm] = va.w;
        __syncthreads();
#pragma unroll
        for (int kk = 0; kk < BK; kk++) {
            float a[4], bk[4], bv[4];
            *(float4*)a  = *(const float4*)&Xs[kk][ty * 4];
            *(float4*)bk = *(const float4*)&Ks[kk][tx * 4];
            *(float4*)bv = *(const float4*)&Vs[kk][tx * 4];
#pragma unroll
            for (int r = 0; r < 4; r++)
#pragma unroll
                for (int c = 0; c < 4; c++) {
                    accK[r][c] += a[r] * bk[c];
                    accV[r][c] += a[r] * bv[c];
                }
        }
        __syncthreads();
    }

    // phi + in-block row reduction
    float pk[4], pkv[4];
#pragma unroll
    for (int c = 0; c < 4; c++) { pk[c] = 0.f; pkv[c] = 0.f; }
#pragma unroll
    for (int r = 0; r < 4; r++)
#pragma unroll
        for (int c = 0; c < 4; c++) {
            float kv = phi_f(accK[r][c]);
            pk[c]  += kv;
            pkv[c] += kv * accV[r][c];
        }
#pragma unroll
    for (int c = 0; c < 4; c++) {
        redk [ty][tx * 4 + c] = pk[c];
        redkv[ty][tx * 4 + c] = pkv[c];
    }
    __syncthreads();
    if (tid < BN) {
        float sk = 0.f, skv = 0.f;
#pragma unroll
        for (int j = 0; j < 16; j++) { sk += redk[j][tid]; skv += redkv[j][tid]; }
        g_pk [(size_t)blockIdx.y * DD + col0 + tid] = sk;
        g_pkv[(size_t)blockIdx.y * DD + col0 + tid] = skv;
    }
}

// ---------------------------------------------------------------------------
// Kernel 2: fold 64 row-block partials per batch -> g_ksum / g_kvsum.
// ---------------------------------------------------------------------------
__global__ void reduce_stats_kernel() {
    int i = blockIdx.x * blockDim.x + threadIdx.x;   // over BB*DD
    if (i >= BB * DD) return;
    int b = i / DD;
    int d = i - b * DD;
    float sk = 0.f, skv = 0.f;
    int rb0 = b * (TT / BM);                          // 64 row blocks per batch
    for (int rb = 0; rb < TT / BM; rb++) {
        sk  += g_pk [(size_t)(rb0 + rb) * DD + d];
        skv += g_pkv[(size_t)(rb0 + rb) * DD + d];
    }
    g_ksum [i] = sk;
    g_kvsum[i] = skv;
}

// ---------------------------------------------------------------------------
// Kernel 3: q = phi(x@Wq^T), g_logit = x@Wg^T for one head (BN=64=HD),
// s = <q, kv_sum>, z = <q, k_sum>+eps per row, then
// out = sigmoid(g+bg)*(s/z) + (1-sigmoid)*x.
// grid = (DD/BN, BB*TT/BM), 256 threads.
// ---------------------------------------------------------------------------
__global__ __launch_bounds__(256) void out_kernel(
    const float* __restrict__ X,
    const float* __restrict__ Wq,
    const float* __restrict__ Wg,
    const float* __restrict__ bg,
    float* __restrict__ out)
{
    __shared__ float Xs[BK][BM + 4];
    __shared__ float Qs[BK][BN + 4];
    __shared__ float Gs[BK][BN + 4];
    __shared__ float red_s[BM][17];
    __shared__ float red_z[BM][17];
    __shared__ float srow[BM];
    __shared__ float zrow[BM];

    const int tid  = threadIdx.x;
    const int tx   = tid & 15;
    const int ty   = tid >> 4;
    const int row0 = blockIdx.y * BM;
    const int col0 = blockIdx.x * BN;     // head-aligned (BN == HD)

    const int lm = tid & 63;
    const int lk = (tid >> 6) << 2;

    const float* xp = X  + (size_t)(row0 + lm) * DD + lk;
    const float* qp = Wq + (size_t)(col0 + lm) * DD + lk;
    const float* gp = Wg + (size_t)(col0 + lm) * DD + lk;

    float accQ[4][4], accG[4][4];
#pragma unroll
    for (int r = 0; r < 4; r++)
#pragma unroll
        for (int c = 0; c < 4; c++) { accQ[r][c] = 0.f; accG[r][c] = 0.f; }

    for (int k0 = 0; k0 < DD; k0 += BK) {
        float4 xa = *(const float4*)(xp + k0);
        float4 qa = *(const float4*)(qp + k0);
        float4 ga = *(const float4*)(gp + k0);
        Xs[lk + 0][lm] = xa.x; Xs[lk + 1][lm] = xa.y; Xs[lk + 2][lm] = xa.z; Xs[lk + 3][lm] = xa.w;
        Qs[lk + 0][lm] = qa.x; Qs[lk + 1][lm] = qa.y; Qs[lk + 2][lm] = qa.z; Qs[lk + 3][lm] = qa.w;
        Gs[lk + 0][lm] = ga.x; Gs[lk + 1][lm] = ga.y; Gs[lk + 2][lm] = ga.z; Gs[lk + 3][lm] = ga.w;
        __syncthreads();
#pragma unroll
        for (int kk = 0; kk < BK; kk++) {
            float a[4], bq[4], bgm[4];
            *(float4*)a   = *(const float4*)&Xs[kk][ty * 4];
            *(float4*)bq  = *(const float4*)&Qs[kk][tx * 4];
            *(float4*)bgm = *(const float4*)&Gs[kk][tx * 4];
#pragma unroll
            for (int r = 0; r < 4; r++)
#pragma unroll
                for (int c = 0; c < 4; c++) {
                    accQ[r][c] += a[r] * bq[c];
                    accG[r][c] += a[r] * bgm[c];
                }
        }
        __syncthreads();
    }

    const int b = row0 / TT;
    float kvs[4], ks[4], bgv[4];
#pragma unroll
    for (int c = 0; c < 4; c++) {
        int gc = col0 + tx * 4 + c;
        kvs[c] = g_kvsum[b * DD + gc];
        ks[c]  = g_ksum [b * DD + gc];
        bgv[c] = bg[gc];
    }

    float sp[4], zp[4];
#pragma unroll
    for (int r = 0; r < 4; r++) { sp[r] = 0.f; zp[r] = 0.f; }
#pragma unroll
    for (int r = 0; r < 4; r++)
#pragma unroll
        for (int c = 0; c < 4; c++) {
            float q = phi_f(accQ[r][c]);
            sp[r] += q * kvs[c];
            zp[r] += q * ks[c];
        }
#pragma unroll
    for (int r = 0; r < 4; r++) {
        red_s[ty * 4 + r][tx] = sp[r];
        red_z[ty * 4 + r][tx] = zp[r];
    }
    __syncthreads();
    if (tid < BM) {
        float s = 0.f, z = 0.f;
#pragma unroll
        for (int j = 0; j < 16; j++) { s += red_s[tid][j]; z += red_z[tid][j]; }
        srow[tid] = s;
        zrow[tid] = z + EPSF;
    }
    __syncthreads();

#pragma unroll
    for (int r = 0; r < 4; r++) {
        int lrow = ty * 4 + r;
        int grow = row0 + lrow;
        float ratio = srow[lrow] / zrow[lrow];
        float4 xv = *(const float4*)&X[(size_t)grow * DD + col0 + tx * 4];
        float4 o;
        {
            float gl, g;
            gl = accG[r][0] + bgv[0]; g = 1.f / (1.f + __expf(-gl)); o.x = g * ratio + (1.f - g) * xv.x;
            gl = accG[r][1] + bgv[1]; g = 1.f / (1.f + __expf(-gl)); o.y = g * ratio + (1.f - g) * xv.y;
            gl = accG[r][2] + bgv[2]; g = 1.f / (1.f + __expf(-gl)); o.z = g * ratio + (1.f - g) * xv.z;
            gl = accG[r][3] + bgv[3]; g = 1.f / (1.f + __expf(-gl)); o.w = g * ratio + (1.f - g) * xv.w;
        }
        *(float4*)&out[(size_t)grow * DD + col0 + tx * 4] = o;
    }
}

// ---------------------------------------------------------------------------
extern "C" void kernel_launch(void* const* d_in, const int* in_sizes, int n_in,
                              void* d_out, int out_size)
{
    const float* x  = (const float*)d_in[0];
    const float* Wq = (const float*)d_in[1];
    const float* Wk = (const float*)d_in[2];
    const float* Wv = (const float*)d_in[3];
    // d_in[4] = Wo — unused by the reference computation
    const float* Wg = (const float*)d_in[5];
    const float* bg = (const float*)d_in[6];
    float* out = (float*)d_out;

    dim3 grid(DD / BN, (BB * TT) / BM);   // (16, 256)
    stats_kernel<<<grid, 256>>>(x, Wk, Wv);
    reduce_stats_kernel<<<(BB * DD + 255) / 256, 256>>>();
    out_kernel<<<grid, 256>>>(x, Wq, Wg, bg, out);
}

// round 2
// speedup vs baseline: 1.0000x; 1.0000x over previous
#include <cuda_runtime.h>
#include <math.h>

#define DD   1024
#define TT   4096
#define BB   4
#define BM   64
#define BN   64
#define BK   16
#define EPSF 1e-6f

// Row-block partials (deterministic two-stage reduction, no float atomics).
// (BB*TT)/BM = 256 row blocks, DD columns each.
__device__ float g_pk [256 * DD];
__device__ float g_pkv[256 * DD];
// Final stats: [B, D] each (D = H*HD flattened).
__device__ float g_ksum [BB * DD];
__device__ float g_kvsum[BB * DD];

__device__ __forceinline__ float phi_f(float x) {
    // elu(x)+1 : x>0 -> x+1 ; x<=0 -> exp(x)
    return x > 0.f ? x + 1.f : __expf(x);
}

// ---------------------------------------------------------------------------
// Kernel 1: k = phi(x@Wk^T), v = x@Wv^T computed tile-wise; reduce over the
// 64 rows of the tile -> per-rowblock partial k_sum / kv_sum.
// grid = (DD/BN, BB*TT/BM), 256 threads.
// ---------------------------------------------------------------------------
__global__ __launch_bounds__(256) void stats_kernel(
    const float* __restrict__ X,
    const float* __restrict__ Wk,
    const float* __restrict__ Wv)
{
    __shared__ float Xs[BK][BM + 4];
    __shared__ float Ks[BK][BN + 4];
    __shared__ float Vs[BK][BN + 4];
    __shared__ float redk [16][BN];
    __shared__ float redkv[16][BN];

    const int tid  = threadIdx.x;
    const int tx   = tid & 15;
    const int ty   = tid >> 4;
    const int row0 = blockIdx.y * BM;
    const int col0 = blockIdx.x * BN;

    const int lm = tid & 63;          // row (X) / out-col (W) index for loads
    const int lk = (tid >> 6) << 2;   // k sub-offset: 0,4,8,12

    const float* xp = X  + (size_t)(row0 + lm) * DD + lk;
    const float* kp = Wk + (size_t)(col0 + lm) * DD + lk;
    const float* vp = Wv + (size_t)(col0 + lm) * DD + lk;

    float accK[4][4], accV[4][4];
#pragma unroll
    for (int r = 0; r < 4; r++)
#pragma unroll
        for (int c = 0; c < 4; c++) { accK[r][c] = 0.f; accV[r][c] = 0.f; }

    for (int k0 = 0; k0 < DD; k0 += BK) {
        float4 xa = *(const float4*)(xp + k0);
        float4 ka = *(const float4*)(kp + k0);
        float4 va = *(const float4*)(vp + k0);
        Xs[lk + 0][lm] = xa.x; Xs[lk + 1][lm] = xa.y; Xs[lk + 2][lm] = xa.z; Xs[lk + 3][lm] = xa.w;
        Ks[lk + 0][lm] = ka.x; Ks[lk + 1][lm] = ka.y; Ks[lk + 2][lm] = ka.z; Ks[lk + 3][lm] = ka.w;
        Vs[lk + 0][lm] = va.x; Vs[lk + 1][lm] = va.y; Vs[lk + 2][lm] = va.z; Vs[lk + 3][lm] = va.w;
        __syncthreads();
#pragma unroll
        for (int kk = 0; kk < BK; kk++) {
            float a[4], bk[4], bv[4];
            *(float4*)a  = *(const float4*)&Xs[kk][ty * 4];
            *(float4*)bk = *(const float4*)&Ks[kk][tx * 4];
            *(float4*)bv = *(const float4*)&Vs[kk][tx * 4];
#pragma unroll
            for (int r = 0; r < 4; r++)
#pragma unroll
                for (int c = 0; c < 4; c++) {
                    accK[r][c] += a[r] * bk[c];
                    accV[r][c] += a[r] * bv[c];
                }
        }
        __syncthreads();
    }

    // phi + in-block row reduction
    float pk[4], pkv[4];
#pragma unroll
    for (int c = 0; c < 4; c++) { pk[c] = 0.f; pkv[c] = 0.f; }
#pragma unroll
    for (int r = 0; r < 4; r++)
#pragma unroll
        for (int c = 0; c < 4; c++) {
            float kv = phi_f(accK[r][c]);
            pk[c]  += kv;
            pkv[c] += kv * accV[r][c];
        }
#pragma unroll
    for (int c = 0; c < 4; c++) {
        redk [ty][tx * 4 + c] = pk[c];
        redkv[ty][tx * 4 + c] = pkv[c];
    }
    __syncthreads();
    if (tid < BN) {
        float sk = 0.f, skv = 0.f;
#pragma unroll
        for (int j = 0; j < 16; j++) { sk += redk[j][tid]; skv += redkv[j][tid]; }
        g_pk [(size_t)blockIdx.y * DD + col0 + tid] = sk;
        g_pkv[(size_t)blockIdx.y * DD + col0 + tid] = skv;
    }
}

// ---------------------------------------------------------------------------
// Kernel 2: fold 64 row-block partials per batch -> g_ksum / g_kvsum.
// ---------------------------------------------------------------------------
__global__ void reduce_stats_kernel() {
    int i = blockIdx.x * blockDim.x + threadIdx.x;   // over BB*DD
    if (i >= BB * DD) return;
    int b = i / DD;
    int d = i - b * DD;
    float sk = 0.f, skv = 0.f;
    int rb0 = b * (TT / BM);                          // 64 row blocks per batch
    for (int rb = 0; rb < TT / BM; rb++) {
        sk  += g_pk [(size_t)(rb0 + rb) * DD + d];
        skv += g_pkv[(size_t)(rb0 + rb) * DD + d];
    }
    g_ksum [i] = sk;
    g_kvsum[i] = skv;
}

// ---------------------------------------------------------------------------
// Kernel 3: q = phi(x@Wq^T), g_logit = x@Wg^T for one head (BN=64=HD),
// s = <q, kv_sum>, z = <q, k_sum>+eps per row, then
// out = sigmoid(g+bg)*(s/z) + (1-sigmoid)*x.
// grid = (DD/BN, BB*TT/BM), 256 threads.
// ---------------------------------------------------------------------------
__global__ __launch_bounds__(256) void out_kernel(
    const float* __restrict__ X,
    const float* __restrict__ Wq,
    const float* __restrict__ Wg,
    const float* __restrict__ bg,
    float* __restrict__ out)
{
    __shared__ float Xs[BK][BM + 4];
    __shared__ float Qs[BK][BN + 4];
    __shared__ float Gs[BK][BN + 4];
    __shared__ float red_s[BM][17];
    __shared__ float red_z[BM][17];
    __shared__ float srow[BM];
    __shared__ float zrow[BM];

    const int tid  = threadIdx.x;
    const int tx   = tid & 15;
    const int ty   = tid >> 4;
    const int row0 = blockIdx.y * BM;
    const int col0 = blockIdx.x * BN;     // head-aligned (BN == HD)

    const int lm = tid & 63;
    const int lk = (tid >> 6) << 2;

    const float* xp = X  + (size_t)(row0 + lm) * DD + lk;
    const float* qp = Wq + (size_t)(col0 + lm) * DD + lk;
    const float* gp = Wg + (size_t)(col0 + lm) * DD + lk;

    float accQ[4][4], accG[4][4];
#pragma unroll
    for (int r = 0; r < 4; r++)
#pragma unroll
        for (int c = 0; c < 4; c++) { accQ[r][c] = 0.f; accG[r][c] = 0.f; }

    for (int k0 = 0; k0 < DD; k0 += BK) {
        float4 xa = *(const float4*)(xp + k0);
        float4 qa = *(const float4*)(qp + k0);
        float4 ga = *(const float4*)(gp + k0);
        Xs[lk + 0][lm] = xa.x; Xs[lk + 1][lm] = xa.y; Xs[lk + 2][lm] = xa.z; Xs[lk + 3][lm] = xa.w;
        Qs[lk + 0][lm] = qa.x; Qs[lk + 1][lm] = qa.y; Qs[lk + 2][lm] = qa.z; Qs[lk + 3][lm] = qa.w;
        Gs[lk + 0][lm] = ga.x; Gs[lk + 1][lm] = ga.y; Gs[lk + 2][lm] = ga.z; Gs[lk + 3][lm] = ga.w;
        __syncthreads();
#pragma unroll
        for (int kk = 0; kk < BK; kk++) {
            float a[4], bq[4], bgm[4];
            *(float4*)a   = *(const float4*)&Xs[kk][ty * 4];
            *(float4*)bq  = *(const float4*)&Qs[kk][tx * 4];
            *(float4*)bgm = *(const float4*)&Gs[kk][tx * 4];
#pragma unroll
            for (int r = 0; r < 4; r++)
#pragma unroll
                for (int c = 0; c < 4; c++) {
                    accQ[r][c] += a[r] * bq[c];
                    accG[r][c] += a[r] * bgm[c];
                }
        }
        __syncthreads();
    }

    const int b = row0 / TT;
    float kvs[4], ks[4], bgv[4];
#pragma unroll
    for (int c = 0; c < 4; c++) {
        int gc = col0 + tx * 4 + c;
        kvs[c] = g_kvsum[b * DD + gc];
        ks[c]  = g_ksum [b * DD + gc];
        bgv[c] = bg[gc];
    }

    float sp[4], zp[4];
#pragma unroll
    for (int r = 0; r < 4; r++) { sp[r] = 0.f; zp[r] = 0.f; }
#pragma unroll
    for (int r = 0; r < 4; r++)
#pragma unroll
        for (int c = 0; c < 4; c++) {
            float q = phi_f(accQ[r][c]);
            sp[r] += q * kvs[c];
            zp[r] += q * ks[c];
        }
#pragma unroll
    for (int r = 0; r < 4; r++) {
        red_s[ty * 4 + r][tx] = sp[r];
        red_z[ty * 4 + r][tx] = zp[r];
    }
    __syncthreads();
    if (tid < BM) {
        float s = 0.f, z = 0.f;
#pragma unroll
        for (int j = 0; j < 16; j++) { s += red_s[tid][j]; z += red_z[tid][j]; }
        srow[tid] = s;
        zrow[tid] = z + EPSF;
    }
    __syncthreads();

#pragma unroll
    for (int r = 0; r < 4; r++) {
        int lrow = ty * 4 + r;
        int grow = row0 + lrow;
        float ratio = srow[lrow] / zrow[lrow];
        float4 xv = *(const float4*)&X[(size_t)grow * DD + col0 + tx * 4];
        float4 o;
        {
            float gl, g;
            gl = accG[r][0] + bgv[0]; g = 1.f / (1.f + __expf(-gl)); o.x = g * ratio + (1.f - g) * xv.x;
            gl = accG[r][1] + bgv[1]; g = 1.f / (1.f + __expf(-gl)); o.y = g * ratio + (1.f - g) * xv.y;
            gl = accG[r][2] + bgv[2]; g = 1.f / (1.f + __expf(-gl)); o.z = g * ratio + (1.f - g) * xv.z;
            gl = accG[r][3] + bgv[3]; g = 1.f / (1.f + __expf(-gl)); o.w = g * ratio + (1.f - g) * xv.w;
        }
        *(float4*)&out[(size_t)grow * DD + col0 + tx * 4] = o;
    }
}

// ---------------------------------------------------------------------------
extern "C" void kernel_launch(void* const* d_in, const int* in_sizes, int n_in,
                              void* d_out, int out_size)
{
    const float* x  = (const float*)d_in[0];
    const float* Wq = (const float*)d_in[1];
    const float* Wk = (const float*)d_in[2];
    const float* Wv = (const float*)d_in[3];
    // d_in[4] = Wo — unused by the reference computation
    const float* Wg = (const float*)d_in[5];
    const float* bg = (const float*)d_in[6];
    float* out = (float*)d_out;

    dim3 grid(DD / BN, (BB * TT) / BM);   // (16, 256)
    stats_kernel<<<grid, 256>>>(x, Wk, Wv);
    reduce_stats_kernel<<<(BB * DD + 255) / 256, 256>>>();
    out_kernel<<<grid, 256>>>(x, Wq, Wg, bg, out);
}

// round 4
// speedup vs baseline: 4.3213x; 4.3211x over previous
#include <cuda_runtime.h>
#include <cstdint>
#include <math.h>

#define DD 1024
#define TT 4096
#define BB 4
#define EPSF 1e-6f

#define BM 128
#define BN 64            // per weight matrix; one head per block in out_kernel
#define BK 32
#define BKP 36           // padded smem row (floats)
#define NCHUNK (DD/BK)   // 32

#define A_TILE_B  (BM*BKP*4)          // 18432
#define B_TILE_B  (BN*BKP*4)          // 9216
#define STAGE_B   (A_TILE_B + 2*B_TILE_B)   // 36864
#define OFF_STATS (2*STAGE_B)               // 73728
#define SMEM_TOTAL (OFF_STATS + 2048)       // 75776

#define NRB (BB*TT/BM)   // 128 row blocks

// Deterministic two-stage reduction buffers
__device__ float g_pk  [NRB*DD];
__device__ float g_pkv [NRB*DD];
__device__ float g_ksum [BB*DD];
__device__ float g_kvsum[BB*DD];

// ---------------------------------------------------------------- helpers ---
__device__ __forceinline__ uint32_t smem_u32(const void* p) {
    uint32_t a;
    asm("{ .reg .u64 t; cvta.to.shared.u64 t, %1; cvt.u32.u64 %0, t; }" : "=r"(a) : "l"(p));
    return a;
}
__device__ __forceinline__ void cp16(uint32_t dst, const void* src) {
    asm volatile("cp.async.cg.shared.global [%0], [%1], 16;" :: "r"(dst), "l"(src));
}
__device__ __forceinline__ void cp_commit() { asm volatile("cp.async.commit_group;" ::: "memory"); }
template <int N> __device__ __forceinline__ void cp_wait() {
    asm volatile("cp.async.wait_group %0;" :: "n"(N) : "memory");
}
__device__ __forceinline__ uint32_t f2tf32(float f) {
    uint32_t o;
    asm("cvt.rna.tf32.f32 %0, %1;" : "=r"(o) : "f"(f));
    return o;
}
__device__ __forceinline__ void mma_tf32(float* d, const uint32_t* a, const uint32_t* b) {
    asm volatile("mma.sync.aligned.m16n8k8.row.col.f32.tf32.tf32.f32 "
                 "{%0,%1,%2,%3}, {%4,%5,%6,%7}, {%8,%9}, {%0,%1,%2,%3};"
                 : "+f"(d[0]), "+f"(d[1]), "+f"(d[2]), "+f"(d[3])
                 : "r"(a[0]), "r"(a[1]), "r"(a[2]), "r"(a[3]), "r"(b[0]), "r"(b[1]));
}
__device__ __forceinline__ float phi_f(float x) { return x > 0.f ? x + 1.f : __expf(x); }
__device__ __forceinline__ float sigm(float x) { return 1.f / (1.f + __expf(-x)); }

// Load tiles of one K-chunk into a stage: A 128x32, B1 64x32, B2 64x32 (fp32)
__device__ __forceinline__ void load_stage(uint32_t sbase,
                                           const float* A, const float* B1, const float* B2,
                                           int tid)
{
#pragma unroll
    for (int p = 0; p < 4; p++) {           // A: 1024 float4 / 256 thr
        int idx = p * 256 + tid;
        int row = idx >> 3, cg = idx & 7;
        cp16(sbase + row * (BKP*4) + cg * 16,
             (const char*)A + (size_t)row * (DD*4) + cg * 16);
    }
#pragma unroll
    for (int p = 0; p < 2; p++) {           // B1: 512 float4
        int idx = p * 256 + tid;
        int row = idx >> 3, cg = idx & 7;
        cp16(sbase + A_TILE_B + row * (BKP*4) + cg * 16,
             (const char*)B1 + (size_t)row * (DD*4) + cg * 16);
    }
#pragma unroll
    for (int p = 0; p < 2; p++) {           // B2: 512 float4
        int idx = p * 256 + tid;
        int row = idx >> 3, cg = idx & 7;
        cp16(sbase + A_TILE_B + B_TILE_B + row * (BKP*4) + cg * 16,
             (const char*)B2 + (size_t)row * (DD*4) + cg * 16);
    }
}

// Double-buffered dual-output GEMM mainloop.
// acc1/acc2: [2 m][4 nt][4 regs]. Warp layout: wm = wid&3 (M), wn = wid>>2 (N).
__device__ __forceinline__ void run_gemm2(char* smem, uint32_t sb,
                                          const float* A, const float* B1, const float* B2,
                                          int tid, float acc1[2][4][4], float acc2[2][4][4])
{
    const int wid = tid >> 5, lane = tid & 31;
    const int wm = wid & 3, wn = wid >> 2;
    const int l4 = lane >> 2, lm4 = lane & 3;

#pragma unroll
    for (int m = 0; m < 2; m++)
#pragma unroll
        for (int nt = 0; nt < 4; nt++)
#pragma unroll
            for (int r = 0; r < 4; r++) { acc1[m][nt][r] = 0.f; acc2[m][nt][r] = 0.f; }

    load_stage(sb, A, B1, B2, tid);
    cp_commit();

    for (int c = 0; c < NCHUNK; c++) {
        const int s = c & 1;
        if (c + 1 < NCHUNK) {
            const int k0 = (c + 1) * BK;
            load_stage(sb + ((c + 1) & 1) * STAGE_B, A + k0, B1 + k0, B2 + k0, tid);
            cp_commit();
            cp_wait<1>();
        } else {
            cp_wait<0>();
        }
        __syncthreads();

        const float* As  = (const float*)(smem + s * STAGE_B);
        const float* B1s = (const float*)(smem + s * STAGE_B + A_TILE_B);
        const float* B2s = (const float*)(smem + s * STAGE_B + A_TILE_B + B_TILE_B);

#pragma unroll
        for (int kk = 0; kk < 4; kk++) {
            const int kc = kk * 8;
            uint32_t af[2][4];
#pragma unroll
            for (int m = 0; m < 2; m++) {
                const int r0 = wm * 32 + m * 16 + l4;
                af[m][0] = f2tf32(As[(r0    ) * BKP + kc + lm4]);
                af[m][1] = f2tf32(As[(r0 + 8) * BKP + kc + lm4]);
                af[m][2] = f2tf32(As[(r0    ) * BKP + kc + lm4 + 4]);
                af[m][3] = f2tf32(As[(r0 + 8) * BKP + kc + lm4 + 4]);
            }
            uint32_t bf1[4][2], bf2[4][2];
#pragma unroll
            for (int nt = 0; nt < 4; nt++) {
                const int n0 = wn * 32 + nt * 8 + l4;
                bf1[nt][0] = f2tf32(B1s[n0 * BKP + kc + lm4]);
                bf1[nt][1] = f2tf32(B1s[n0 * BKP + kc + lm4 + 4]);
                bf2[nt][0] = f2tf32(B2s[n0 * BKP + kc + lm4]);
                bf2[nt][1] = f2tf32(B2s[n0 * BKP + kc + lm4 + 4]);
            }
#pragma unroll
            for (int m = 0; m < 2; m++)
#pragma unroll
                for (int nt = 0; nt < 4; nt++) {
                    mma_tf32(acc1[m][nt], af[m], bf1[nt]);
                    mma_tf32(acc2[m][nt], af[m], bf2[nt]);
                }
        }
        __syncthreads();
    }
}

// ---------------------------------------------------------------------------
// Kernel 1: K=phi(X@Wk^T), V=X@Wv^T; per-rowblock column sums of phi(K), phi(K)*V
// grid = (DD/BN=16, NRB=128), 256 threads
// ---------------------------------------------------------------------------
__global__ void __launch_bounds__(256)
stats_kernel(const float* __restrict__ X, const float* __restrict__ Wk,
             const float* __restrict__ Wv)
{
    extern __shared__ char smem[];
    uint32_t sb = smem_u32(smem);
    const int tid = threadIdx.x;
    const int row0 = blockIdx.y * BM, col0 = blockIdx.x * BN;

    float accK[2][4][4], accV[2][4][4];
    run_gemm2(smem, sb, X + (size_t)row0 * DD, Wk + (size_t)col0 * DD,
              Wv + (size_t)col0 * DD, tid, accK, accV);

    // Stage phi(K) and phi(K)*V into smem [128][66]
    float* stA = (float*)smem;               // [128][66]
    float* stB = stA + 128 * 66;             // [128][66]
    const int wid = tid >> 5, lane = tid & 31;
    const int wm = wid & 3, wn = wid >> 2;
    const int l4 = lane >> 2, lm4 = lane & 3;

#pragma unroll
    for (int m = 0; m < 2; m++)
#pragma unroll
        for (int nt = 0; nt < 4; nt++) {
            const int col = wn * 32 + nt * 8 + lm4 * 2;
#pragma unroll
            for (int half = 0; half < 2; half++) {
                const int row = wm * 32 + m * 16 + l4 + half * 8;
#pragma unroll
                for (int cc = 0; cc < 2; cc++) {
                    float kv = phi_f(accK[m][nt][half * 2 + cc]);
                    stA[row * 66 + col + cc] = kv;
                    stB[row * 66 + col + cc] = kv * accV[m][nt][half * 2 + cc];
                }
            }
        }
    __syncthreads();

    // Column reduce: 4 quarters of 32 rows, then fold
    float* partA = (float*)(smem + OFF_STATS);        // [4][64]
    float* partB = partA + 256;                       // [4][64]
    {
        const int col = tid & 63, q = tid >> 6;
        float sa = 0.f, sv = 0.f;
#pragma unroll
        for (int r = 0; r < 32; r++) {
            const int row = q * 32 + r;
            sa += stA[row * 66 + col];
            sv += stB[row * 66 + col];
        }
        partA[q * 64 + col] = sa;
        partB[q * 64 + col] = sv;
    }
    __syncthreads();
    if (tid < 64) {
        float sa = partA[tid] + partA[64 + tid] + partA[128 + tid] + partA[192 + tid];
        float sv = partB[tid] + partB[64 + tid] + partB[128 + tid] + partB[192 + tid];
        size_t o = (size_t)blockIdx.y * DD + col0 + tid;
        g_pk[o]  = sa;
        g_pkv[o] = sv;
    }
}

// ---------------------------------------------------------------------------
// Kernel 2: fold 32 row-block partials per batch
// ---------------------------------------------------------------------------
__global__ void reduce_stats_kernel() {
    int i = blockIdx.x * blockDim.x + threadIdx.x;
    if (i >= BB * DD) return;
    int b = i >> 10, d = i & 1023;
    float sk = 0.f, skv = 0.f;
    int rb0 = b * (NRB / BB);
    for (int rb = 0; rb < NRB / BB; rb++) {
        sk  += g_pk [(size_t)(rb0 + rb) * DD + d];
        skv += g_pkv[(size_t)(rb0 + rb) * DD + d];
    }
    g_ksum[i]  = sk;
    g_kvsum[i] = skv;
}

// ---------------------------------------------------------------------------
// Kernel 3: Q=phi(X@Wq^T), G=X@Wg^T; s,z per row; gated output.
// grid = (16, 128); block column == one head (BN = HD = 64).
// ---------------------------------------------------------------------------
__global__ void __launch_bounds__(256)
out_kernel(const float* __restrict__ X, const float* __restrict__ Wq,
           const float* __restrict__ Wg, const float* __restrict__ bgv,
           float* __restrict__ out)
{
    extern __shared__ char smem[];
    uint32_t sb = smem_u32(smem);
    const int tid = threadIdx.x;
    const int row0 = blockIdx.y * BM, col0 = blockIdx.x * BN;
    const int b = row0 / TT;

    // Dedicated (non-aliased) stats region
    float* kvsS  = (float*)(smem + OFF_STATS);   // [64]
    float* ksS   = kvsS + 64;                    // [64]
    float* bgS   = ksS + 64;                     // [64]
    float* ratio = bgS + 64;                     // [128]
    if (tid < 64) {
        kvsS[tid] = g_kvsum[b * DD + col0 + tid];
        ksS[tid]  = g_ksum [b * DD + col0 + tid];
        bgS[tid]  = bgv[col0 + tid];
    }
    __syncthreads();

    float accQ[2][4][4], accG[2][4][4];
    run_gemm2(smem, sb, X + (size_t)row0 * DD, Wq + (size_t)col0 * DD,
              Wg + (size_t)col0 * DD, tid, accQ, accG);

    const int wid = tid >> 5, lane = tid & 31;
    const int wm = wid & 3, wn = wid >> 2;
    const int l4 = lane >> 2, lm4 = lane & 3;

    // Partial s,z per (row, thread-slice): 8 partials per row
    float* red_s = (float*)smem;          // [128][8]
    float* red_z = red_s + 128 * 8;       // [128][8]
    const int sl = wn * 4 + lm4;
#pragma unroll
    for (int m = 0; m < 2; m++)
#pragma unroll
        for (int half = 0; half < 2; half++) {
            const int row = wm * 32 + m * 16 + l4 + half * 8;
            float s = 0.f, z = 0.f;
#pragma unroll
            for (int nt = 0; nt < 4; nt++) {
                const int col = wn * 32 + nt * 8 + lm4 * 2;
#pragma unroll
                for (int cc = 0; cc < 2; cc++) {
                    float q = phi_f(accQ[m][nt][half * 2 + cc]);
                    s += q * kvsS[col + cc];
                    z += q * ksS[col + cc];
                }
            }
            red_s[row * 8 + sl] = s;
            red_z[row * 8 + sl] = z;
        }
    __syncthreads();
    if (tid < 128) {
        float s = 0.f, z = 0.f;
#pragma unroll
        for (int j = 0; j < 8; j++) { s += red_s[tid * 8 + j]; z += red_z[tid * 8 + j]; }
        ratio[tid] = s / (z + EPSF);
    }
    __syncthreads();

    // Gate + mix, direct float2 stores
#pragma unroll
    for (int m = 0; m < 2; m++)
#pragma unroll
        for (int half = 0; half < 2; half++) {
            const int row = wm * 32 + m * 16 + l4 + half * 8;
            const float rt = ratio[row];
            const size_t rbase = (size_t)(row0 + row) * DD + col0;
#pragma unroll
            for (int nt = 0; nt < 4; nt++) {
                const int col = wn * 32 + nt * 8 + lm4 * 2;
                const float2 x2 = *(const float2*)&X[rbase + col];
                float g0 = sigm(accG[m][nt][half * 2 + 0] + bgS[col + 0]);
                float g1 = sigm(accG[m][nt][half * 2 + 1] + bgS[col + 1]);
                float2 o;
                o.x = g0 * rt + (1.f - g0) * x2.x;
                o.y = g1 * rt + (1.f - g1) * x2.y;
                *(float2*)&out[rbase + col] = o;
            }
        }
}

// ---------------------------------------------------------------------------
extern "C" void kernel_launch(void* const* d_in, const int* in_sizes, int n_in,
                              void* d_out, int out_size)
{
    const float* x  = (const float*)d_in[0];
    const float* Wq = (const float*)d_in[1];
    const float* Wk = (const float*)d_in[2];
    const float* Wv = (const float*)d_in[3];
    // d_in[4] = Wo — unused by the reference computation
    const float* Wg = (const float*)d_in[5];
    const float* bg = (const float*)d_in[6];
    float* out = (float*)d_out;

    cudaFuncSetAttribute(stats_kernel, cudaFuncAttributeMaxDynamicSharedMemorySize, SMEM_TOTAL);
    cudaFuncSetAttribute(out_kernel,   cudaFuncAttributeMaxDynamicSharedMemorySize, SMEM_TOTAL);

    dim3 grid(DD / BN, NRB);   // (16, 128)
    stats_kernel<<<grid, 256, SMEM_TOTAL>>>(x, Wk, Wv);
    reduce_stats_kernel<<<(BB * DD + 255) / 256, 256>>>();
    out_kernel<<<grid, 256, SMEM_TOTAL>>>(x, Wq, Wg, bg, out);
}